// round 17
// baseline (speedup 1.0000x reference)
#include <cuda_runtime.h>

#define NN 100000
#define EE 1600000
#define LL 4
#define BNE 1e-5f
#define NT1 1563  // ceil(NN/64)
#define NTC 3125  // ceil(NN/32)
#define PGRID 592

typedef unsigned long long ull;
typedef ulonglong2 ullv2;

// ---------------- static device scratch ----------------
__device__ float g_h[(size_t)NN * 64];
__device__ float g_hi[(size_t)NN * 64];
__device__ float g_aggr[(size_t)NN * 64];
__device__ float g_z1[(size_t)NN * 64];
__device__ float g_y1[(size_t)NN * 128];
__device__ float g_stats[1280];

__device__ __forceinline__ float lrelu(float v) { return v > 0.f ? v : 0.01f * v; }

__device__ __forceinline__ void ffma2(ull& acc, ull a, ull b) {
    asm("fma.rn.f32x2 %0, %1, %2, %0;" : "+l"(acc) : "l"(a), "l"(b));
}
__device__ __forceinline__ ull packf2(float lo, float hi) {
    union { float2 f; ull u; } t; t.f = make_float2(lo, hi); return t.u;
}
__device__ __forceinline__ float2 unpackf2(ull v) {
    union { float2 f; ull u; } t; t.u = v; return t.f;
}

// ---------------- zero stats ----------------
__global__ void k_zero() {
    int i = blockIdx.x * 256 + threadIdx.x;
    if (i < 1280) g_stats[i] = 0.f;
}

// ---------------- column stats (sum, sumsq) ----------------
template <int C>
__global__ void __launch_bounds__(256) k_stats(const float* __restrict__ src, int off) {
    const int RPI = 256 / C;
    int tid = threadIdx.x;
    int c = tid % C;
    int rg = tid / C;
    float s = 0.f, q = 0.f;
    for (int r = blockIdx.x * RPI + rg; r < NN; r += gridDim.x * RPI) {
        float v = src[(size_t)r * C + c];
        s += v; q += v * v;
    }
    __shared__ float sm[256], sq[256];
    sm[tid] = s; sq[tid] = q;
    __syncthreads();
    if (tid < C) {
#pragma unroll
        for (int g2 = 1; g2 < RPI; ++g2) { s += sm[tid + g2 * C]; q += sq[tid + g2 * C]; }
        atomicAdd(&g_stats[off + tid], s);
        atomicAdd(&g_stats[off + C + tid], q);
    }
}

// ---------------- pre-BN (+optional leaky) -> g_hi ; zero g_aggr ----------------
__global__ void __launch_bounds__(256) k_bn_pre(const float* __restrict__ in, int off,
                                                const float* __restrict__ w,
                                                const float* __restrict__ b, int leaky) {
    __shared__ float sScl[64], sShf[64];
    int tid = threadIdx.x;
    if (tid < 64) {
        float mean = g_stats[off + tid] * (1.f / NN);
        float var = g_stats[off + 64 + tid] * (1.f / NN) - mean * mean;
        float scl = w[tid] * rsqrtf(var + BNE);
        sScl[tid] = scl;
        sShf[tid] = b[tid] - mean * scl;
    }
    __syncthreads();
    int idx = blockIdx.x * 256 + tid;  // over NN*16 float4s (exact)
    float4 v = ((const float4*)in)[idx];
    int c = (idx & 15) * 4;
    float4 o;
    o.x = fmaf(v.x, sScl[c + 0], sShf[c + 0]);
    o.y = fmaf(v.y, sScl[c + 1], sShf[c + 1]);
    o.z = fmaf(v.z, sScl[c + 2], sShf[c + 2]);
    o.w = fmaf(v.w, sScl[c + 3], sShf[c + 3]);
    if (leaky) { o.x = lrelu(o.x); o.y = lrelu(o.y); o.z = lrelu(o.z); o.w = lrelu(o.w); }
    ((float4*)g_hi)[idx] = o;
    ((float4*)g_aggr)[idx] = make_float4(0.f, 0.f, 0.f, 0.f);
}

// ---------------- edge kernel: double-buffered staging (R13, best) ----------
__global__ void __launch_bounds__(256, 3) k_edge(const int* __restrict__ src,
                                                 const int* __restrict__ dst,
                                                 const float4* __restrict__ ea4,
                                                 const float* __restrict__ W,
                                                 const float* __restrict__ B) {
    __shared__ __align__(16) float sEA[2][64 * 20];
    __shared__ int sSrc[2][64], sDst[2][64];
    int tid = threadIdx.x;
    int lane = tid & 31, warp = tid >> 5;
    int d0 = lane * 2;
    ull wk0[8], wk1[8];
    const ull* Wp = (const ull*)W;
#pragma unroll
    for (int kp = 0; kp < 8; ++kp) {
        wk0[kp] = __ldg(Wp + d0 * 8 + kp);
        wk1[kp] = __ldg(Wp + d0 * 8 + 8 + kp);
    }
    float b0 = __ldg(B + d0), b1 = __ldg(B + d0 + 1);
    const float2* hi2 = (const float2*)g_hi;
    int eTile = tid >> 2, q = tid & 3;
    const int NT = EE / 64;
    const int stride = gridDim.x;
    int t0 = blockIdx.x;
    {
        int tb = t0 * 64;
        *(float4*)(&sEA[0][eTile * 20 + q * 4]) =
            __ldg(ea4 + (size_t)(tb + eTile) * 4 + q);
        if (tid < 64) sSrc[0][tid] = __ldg(src + tb + tid);
        else if (tid < 128) sDst[0][tid - 64] = __ldg(dst + tb + tid - 64);
    }
    __syncthreads();
    int p = 0;
    for (int t = t0; t < NT; t += stride, p ^= 1) {
        int tn = t + stride;
        if (tn < NT) {
            int tb = tn * 64;
            *(float4*)(&sEA[p ^ 1][eTile * 20 + q * 4]) =
                __ldg(ea4 + (size_t)(tb + eTile) * 4 + q);
            if (tid < 64) sSrc[p ^ 1][tid] = __ldg(src + tb + tid);
            else if (tid < 128) sDst[p ^ 1][tid - 64] = __ldg(dst + tb + tid - 64);
        }
        int e0 = warp * 8;
        float2 g[8];
#pragma unroll
        for (int j = 0; j < 8; ++j)
            g[j] = __ldg(hi2 + (size_t)sSrc[p][e0 + j] * 32 + lane);
#pragma unroll
        for (int j = 0; j < 8; ++j) {
            const ullv2* ep = (const ullv2*)(&sEA[p][(e0 + j) * 20]);
            ull acc0 = packf2(b0, 0.f), acc1 = packf2(b1, 0.f);
#pragma unroll
            for (int i = 0; i < 4; ++i) {
                ullv2 pr = ep[i];
                ffma2(acc0, pr.x, wk0[2 * i]);
                ffma2(acc1, pr.x, wk1[2 * i]);
                ffma2(acc0, pr.y, wk0[2 * i + 1]);
                ffma2(acc1, pr.y, wk1[2 * i + 1]);
            }
            float2 a0 = unpackf2(acc0), a1 = unpackf2(acc1);
            float m0 = fmaxf(g[j].x + a0.x + a0.y, 0.f);
            float m1 = fmaxf(g[j].y + a1.x + a1.y, 0.f);
            float* pp = g_aggr + (size_t)sDst[p][e0 + j] * 64 + d0;
            asm volatile("red.global.add.v2.f32 [%0], {%1, %2};" ::"l"(pp), "f"(m0),
                         "f"(m1) : "memory");
        }
        __syncthreads();
    }
}

// ---- 2-row k-pair FFMA2 GEMM: 8 outputs x 2 rows, 32 k-pairs ----
// thread (r2, g8): rows r2, r2+ROFF; outputs g8*8 .. g8*8+7
#define GEMM_KP2(OUTS, SINP, ROFF)                                        \
    ull accA[8], accB[8];                                                 \
    _Pragma("unroll")                                                     \
    for (int c = 0; c < 8; ++c) {                                         \
        accA[c] = packf2(sB[g8 * 8 + c], 0.f);                            \
        accB[c] = accA[c];                                                \
    }                                                                     \
    _Pragma("unroll 4")                                                   \
    for (int kp = 0; kp < 32; ++kp) {                                     \
        ull a2a = *(const ull*)((SINP) + r2 * 66 + 2 * kp);               \
        ull a2b = *(const ull*)((SINP) + (r2 + ROFF) * 66 + 2 * kp);      \
        const ullv2* wp = (const ullv2*)(sW2 + kp * OUTS + g8 * 8);       \
        _Pragma("unroll")                                                 \
        for (int i = 0; i < 4; ++i) {                                     \
            ullv2 w = wp[i];                                              \
            ffma2(accA[2 * i], a2a, w.x);                                 \
            ffma2(accA[2 * i + 1], a2a, w.y);                             \
            ffma2(accB[2 * i], a2b, w.x);                                 \
            ffma2(accB[2 * i + 1], a2b, w.y);                             \
        }                                                                 \
    }                                                                     \
    float fA[8], fB[8];                                                   \
    _Pragma("unroll")                                                     \
    for (int c = 0; c < 8; ++c) {                                         \
        float2 ta = unpackf2(accA[c]);                                    \
        float2 tb = unpackf2(accB[c]);                                    \
        fA[c] = ta.x + ta.y;                                              \
        fB[c] = tb.x + tb.y;                                              \
    }

// warp-shuffle stats: warp g8 owns columns g8*8..+7 over all rows; no syncs
#define STATS_SHFL(soff)                                                  \
    {                                                                     \
        _Pragma("unroll")                                                 \
        for (int c = 0; c < 8; ++c) {                                     \
            float sA = actA ? fA[c] : 0.f;                                \
            float sBv = actB ? fB[c] : 0.f;                               \
            float s = sA + sBv;                                           \
            float q = sA * sA + sBv * sBv;                                \
            _Pragma("unroll")                                             \
            for (int o = 16; o > 0; o >>= 1) {                            \
                s += __shfl_xor_sync(0xffffffffu, s, o);                  \
                q += __shfl_xor_sync(0xffffffffu, q, o);                  \
            }                                                             \
            if (r2 == 0) {                                                \
                atomicAdd(&g_stats[(soff) + g8 * 8 + c], s);              \
                atomicAdd(&g_stats[(soff) + 64 + g8 * 8 + c], q);         \
            }                                                             \
        }                                                                 \
    }

// ---------------- lin1 (persistent, 2-row, shfl-stats): z1 = ((1+eps)*hi + aggr) @ W^T + b ----
__global__ void __launch_bounds__(256, 4) k_lin1(const float* __restrict__ W,
                                                 const float* __restrict__ B,
                                                 const float* __restrict__ eps, int layer,
                                                 int soff) {
    __shared__ __align__(16) float sIn[64 * 66];
    __shared__ ull sW2[32 * 64];
    __shared__ float sB[64];
    int tid = threadIdx.x;
    float* sWf = (float*)sW2;
#pragma unroll
    for (int j = 0; j < 16; ++j) {
        int idx = tid + j * 256;
        int c = idx >> 6, k = idx & 63;
        sWf[((k >> 1) * 64 + c) * 2 + (k & 1)] = W[idx];
    }
    if (tid < 64) sB[tid] = B[tid];
    float ep = 1.f + __ldg(eps + layer);
    const float4* hi4 = (const float4*)g_hi;
    const float4* ag4 = (const float4*)g_aggr;
    int r2 = tid & 31, g8 = tid >> 5;
    __syncthreads();
    for (int t = blockIdx.x; t < NT1; t += gridDim.x) {
        int base = t * 64;
        int cnt = min(64, NN - base);
#pragma unroll
        for (int j = 0; j < 4; ++j) {
            int f4 = tid + j * 256;
            int rr = f4 >> 4, cc = (f4 & 15) * 4;
            if (rr < cnt) {
                float4 a = hi4[(size_t)(base + rr) * 16 + (f4 & 15)];
                float4 gg = ag4[(size_t)(base + rr) * 16 + (f4 & 15)];
                sIn[rr * 66 + cc + 0] = fmaf(a.x, ep, gg.x);
                sIn[rr * 66 + cc + 1] = fmaf(a.y, ep, gg.y);
                sIn[rr * 66 + cc + 2] = fmaf(a.z, ep, gg.z);
                sIn[rr * 66 + cc + 3] = fmaf(a.w, ep, gg.w);
            }
        }
        __syncthreads();
        bool actA = r2 < cnt, actB = (r2 + 32) < cnt;
        GEMM_KP2(64, sIn, 32)
        if (actA) {
            float4* o = (float4*)(g_z1 + (size_t)(base + r2) * 64 + g8 * 8);
            o[0] = make_float4(fA[0], fA[1], fA[2], fA[3]);
            o[1] = make_float4(fA[4], fA[5], fA[6], fA[7]);
        }
        if (actB) {
            float4* o = (float4*)(g_z1 + (size_t)(base + r2 + 32) * 64 + g8 * 8);
            o[0] = make_float4(fB[0], fB[1], fB[2], fB[3]);
            o[1] = make_float4(fB[4], fB[5], fB[6], fB[7]);
        }
        STATS_SHFL(soff)
        __syncthreads();
    }
}

// ---------------- lin2 (persistent, 2-row, shfl-stats): h = [h +] (leaky(bn(z1)) @ W^T + b) ----
__global__ void __launch_bounds__(256, 4) k_lin2(int statin, const float* __restrict__ bnw,
                                                 const float* __restrict__ bnb,
                                                 const float* __restrict__ W,
                                                 const float* __restrict__ B, int residual,
                                                 int statout) {
    __shared__ __align__(16) float sIn[64 * 66];
    __shared__ ull sW2[32 * 64];
    __shared__ float sB[64], sScl[64], sShf[64];
    int tid = threadIdx.x;
    float* sWf = (float*)sW2;
#pragma unroll
    for (int j = 0; j < 16; ++j) {
        int idx = tid + j * 256;
        int c = idx >> 6, k = idx & 63;
        sWf[((k >> 1) * 64 + c) * 2 + (k & 1)] = W[idx];
    }
    if (tid < 64) {
        sB[tid] = B[tid];
        float mean = g_stats[statin + tid] * (1.f / NN);
        float var = g_stats[statin + 64 + tid] * (1.f / NN) - mean * mean;
        float scl = bnw[tid] * rsqrtf(var + BNE);
        sScl[tid] = scl;
        sShf[tid] = bnb[tid] - mean * scl;
    }
    const float4* z4 = (const float4*)g_z1;
    int r2 = tid & 31, g8 = tid >> 5;
    __syncthreads();
    for (int t = blockIdx.x; t < NT1; t += gridDim.x) {
        int base = t * 64;
        int cnt = min(64, NN - base);
#pragma unroll
        for (int j = 0; j < 4; ++j) {
            int f4 = tid + j * 256;
            int rr = f4 >> 4, cc = (f4 & 15) * 4;
            if (rr < cnt) {
                float4 a = z4[(size_t)(base + rr) * 16 + (f4 & 15)];
                sIn[rr * 66 + cc + 0] = lrelu(fmaf(a.x, sScl[cc + 0], sShf[cc + 0]));
                sIn[rr * 66 + cc + 1] = lrelu(fmaf(a.y, sScl[cc + 1], sShf[cc + 1]));
                sIn[rr * 66 + cc + 2] = lrelu(fmaf(a.z, sScl[cc + 2], sShf[cc + 2]));
                sIn[rr * 66 + cc + 3] = lrelu(fmaf(a.w, sScl[cc + 3], sShf[cc + 3]));
            }
        }
        __syncthreads();
        bool actA = r2 < cnt, actB = (r2 + 32) < cnt;
        GEMM_KP2(64, sIn, 32)
        if (actA) {
            float4* o = (float4*)(g_h + (size_t)(base + r2) * 64 + g8 * 8);
            if (residual) {
                float4 h0 = o[0], h1 = o[1];
                fA[0] += h0.x; fA[1] += h0.y; fA[2] += h0.z; fA[3] += h0.w;
                fA[4] += h1.x; fA[5] += h1.y; fA[6] += h1.z; fA[7] += h1.w;
            }
            o[0] = make_float4(fA[0], fA[1], fA[2], fA[3]);
            o[1] = make_float4(fA[4], fA[5], fA[6], fA[7]);
        }
        if (actB) {
            float4* o = (float4*)(g_h + (size_t)(base + r2 + 32) * 64 + g8 * 8);
            if (residual) {
                float4 h0 = o[0], h1 = o[1];
                fB[0] += h0.x; fB[1] += h0.y; fB[2] += h0.z; fB[3] += h0.w;
                fB[4] += h1.x; fB[5] += h1.y; fB[6] += h1.z; fB[7] += h1.w;
            }
            o[0] = make_float4(fB[0], fB[1], fB[2], fB[3]);
            o[1] = make_float4(fB[4], fB[5], fB[6], fB[7]);
        }
        if (statout >= 0) STATS_SHFL(statout)
        __syncthreads();
    }
}

// ---------------- cls1 (persistent, 2-row threads): y1 = h @ W^T + b  (64 -> 128) ----
__global__ void __launch_bounds__(256, 4) k_cls1(const float* __restrict__ W,
                                                 const float* __restrict__ B) {
    __shared__ __align__(16) float sIn[32 * 66];
    __shared__ ull sW2[32 * 128];
    __shared__ float sB[128];
    int tid = threadIdx.x;
    float* sWf = (float*)sW2;
#pragma unroll
    for (int j = 0; j < 32; ++j) {
        int idx = tid + j * 256;
        int c = idx >> 6, k = idx & 63;
        sWf[((k >> 1) * 128 + c) * 2 + (k & 1)] = W[idx];
    }
    if (tid < 128) sB[tid] = B[tid];
    const float4* h4 = (const float4*)g_h;
    int r2 = tid & 15, g8 = tid >> 4;  // 16 output-groups of 8
    __syncthreads();
    for (int t = blockIdx.x; t < NTC; t += gridDim.x) {
        int base = t * 32;
        int cnt = min(32, NN - base);
#pragma unroll
        for (int j = 0; j < 2; ++j) {
            int f4 = tid + j * 256;
            int rr = f4 >> 4, cc = (f4 & 15) * 4;
            if (rr < cnt) {
                float4 a = h4[(size_t)(base + rr) * 16 + (f4 & 15)];
                sIn[rr * 66 + cc + 0] = a.x;
                sIn[rr * 66 + cc + 1] = a.y;
                sIn[rr * 66 + cc + 2] = a.z;
                sIn[rr * 66 + cc + 3] = a.w;
            }
        }
        __syncthreads();
        bool actA = r2 < cnt, actB = (r2 + 16) < cnt;
        GEMM_KP2(128, sIn, 16)
        if (actA) {
            float4* o = (float4*)(g_y1 + (size_t)(base + r2) * 128 + g8 * 8);
            o[0] = make_float4(fA[0], fA[1], fA[2], fA[3]);
            o[1] = make_float4(fA[4], fA[5], fA[6], fA[7]);
        }
        if (actB) {
            float4* o = (float4*)(g_y1 + (size_t)(base + r2 + 16) * 128 + g8 * 8);
            o[0] = make_float4(fB[0], fB[1], fB[2], fB[3]);
            o[1] = make_float4(fB[4], fB[5], fB[6], fB[7]);
        }
        __syncthreads();
    }
}

// ---------------- cls2: out = leaky(bn(y1)) @ w2 + b2 ----------------
__global__ void __launch_bounds__(256) k_cls2(int off, const float* __restrict__ bnw,
                                              const float* __restrict__ bnb,
                                              const float* __restrict__ w2,
                                              const float* __restrict__ b2,
                                              float* __restrict__ out) {
    __shared__ float sScl[128], sShf[128], sW[128];
    int tid = threadIdx.x;
    if (tid < 128) {
        float mean = g_stats[off + tid] * (1.f / NN);
        float var = g_stats[off + 128 + tid] * (1.f / NN) - mean * mean;
        float scl = bnw[tid] * rsqrtf(var + BNE);
        sScl[tid] = scl;
        sShf[tid] = bnb[tid] - mean * scl;
        sW[tid] = w2[tid];
    }
    __syncthreads();
    int n = blockIdx.x * 256 + tid;
    if (n >= NN) return;
    const float4* row = (const float4*)(g_y1 + (size_t)n * 128);
    float acc = 0.f;
#pragma unroll 8
    for (int m4 = 0; m4 < 32; ++m4) {
        float4 v = row[m4];
        int m = m4 * 4;
        acc += lrelu(fmaf(v.x, sScl[m + 0], sShf[m + 0])) * sW[m + 0];
        acc += lrelu(fmaf(v.y, sScl[m + 1], sShf[m + 1])) * sW[m + 1];
        acc += lrelu(fmaf(v.z, sScl[m + 2], sShf[m + 2])) * sW[m + 2];
        acc += lrelu(fmaf(v.w, sScl[m + 3], sShf[m + 3])) * sW[m + 3];
    }
    out[n] = acc + __ldg(b2);
}

// ---------------- launcher ----------------
extern "C" void kernel_launch(void* const* d_in, const int* in_sizes, int n_in,
                              void* d_out, int out_size) {
    const float* x = (const float*)d_in[0];
    const int* ei = (const int*)d_in[1];
    const float* ea = (const float*)d_in[2];
    const float* bn_pre_w = (const float*)d_in[3];
    const float* bn_pre_b = (const float*)d_in[4];
    const float* edge_lin_w = (const float*)d_in[5];
    const float* edge_lin_b = (const float*)d_in[6];
    const float* lin1_w = (const float*)d_in[7];
    const float* lin1_b = (const float*)d_in[8];
    const float* bn_mid_w = (const float*)d_in[9];
    const float* bn_mid_b = (const float*)d_in[10];
    const float* lin2_w = (const float*)d_in[11];
    const float* lin2_b = (const float*)d_in[12];
    const float* eps = (const float*)d_in[13];
    const float* cls1_w = (const float*)d_in[14];
    const float* cls1_b = (const float*)d_in[15];
    const float* cls_bn_w = (const float*)d_in[16];
    const float* cls_bn_b = (const float*)d_in[17];
    const float* cls2_w = (const float*)d_in[18];
    const float* cls2_b = (const float*)d_in[19];
    float* out = (float*)d_out;
    const int* srcp = ei;
    const int* dstp = ei + EE;

    float *hP, *y1P;
    cudaGetSymbolAddress((void**)&hP, g_h);
    cudaGetSymbolAddress((void**)&y1P, g_y1);

    k_zero<<<5, 256>>>();
    k_stats<64><<<512, 256>>>(x, 0);
    for (int i = 0; i < LL; ++i) {
        const float* hin = (i == 0) ? x : hP;
        k_bn_pre<<<6250, 256>>>(hin, i * 128, bn_pre_w + i * 64, bn_pre_b + i * 64, i > 0);
        k_edge<<<1250, 256>>>(srcp, dstp, (const float4*)ea, edge_lin_w + i * 1024,
                              edge_lin_b + i * 64);
        k_lin1<<<PGRID, 256>>>(lin1_w + i * 4096, lin1_b + i * 64, eps, i, 512 + i * 128);
        k_lin2<<<PGRID, 256>>>(512 + i * 128, bn_mid_w + i * 64, bn_mid_b + i * 64,
                               lin2_w + i * 4096, lin2_b + i * 64, i > 0,
                               (i < 3) ? (i + 1) * 128 : -1);
    }
    k_cls1<<<PGRID, 256>>>(cls1_w, cls1_b);
    k_stats<128><<<512, 256>>>(y1P, 1024);
    k_cls2<<<391, 256>>>(1024, cls_bn_w, cls_bn_b, cls2_w, cls2_b, out);
}